// round 2
// baseline (speedup 1.0000x reference)
#include <cuda_runtime.h>
#include <cuda_bf16.h>
#include <math.h>

// ---------------------------------------------------------------------------
// Problem constants
// ---------------------------------------------------------------------------
#define NV    50000      // nodes
#define NE    800000     // edges (before self loops)
#define ET    (NE + NV)  // edges + self loops
#define F_IN  128
#define H1_   4
#define C1_   64
#define HC1   256        // H1*C1
#define C2_   128
#define NG    32         // graphs
#define NCLS  5

// ---------------------------------------------------------------------------
// Scratch layout
// ---------------------------------------------------------------------------
static const size_t OFF_H1     = 0;
static const size_t OFF_H2     = OFF_H1 + (size_t)NV * 256;
static const size_t OFF_ASRC1  = OFF_H2 + (size_t)NV * 128;
static const size_t OFF_ADST1  = OFF_ASRC1 + (size_t)NV * 4;
static const size_t OFF_ASRC2  = OFF_ADST1 + (size_t)NV * 4;
static const size_t OFF_ADST2  = OFF_ASRC2 + (size_t)NV;
static const size_t OFF_ECO1   = OFF_ADST2 + (size_t)NV;
static const size_t OFF_ECO2   = OFF_ECO1 + (size_t)ET * 4;
static const size_t OFF_ZERO   = OFF_ECO2 + (size_t)ET;      // zero region begins
static const size_t OFF_AGG1   = OFF_ZERO;
static const size_t OFF_AGG2   = OFF_AGG1 + (size_t)NV * 256;
static const size_t OFF_DEN1   = OFF_AGG2 + (size_t)NV * 128;
static const size_t OFF_DEN2   = OFF_DEN1 + (size_t)NV * 4;
static const size_t OFF_POOL   = OFF_DEN2 + (size_t)NV;
static const size_t OFF_CNT    = OFF_POOL + (size_t)NG * 128;
static const size_t ZERO_COUNT = OFF_CNT + NG - OFF_ZERO;
static const size_t OFF_AMAX   = OFF_CNT + NG;               // int region
static const size_t AMAX_COUNT = (size_t)NV * 4 + NV;
static const size_t TOTAL_F    = OFF_AMAX + AMAX_COUNT;

__device__ float g_scratch[TOTAL_F];

// ---------------------------------------------------------------------------
// helpers
// ---------------------------------------------------------------------------
__device__ __forceinline__ int fenc(float f) {
    int i = __float_as_int(f);
    return i >= 0 ? i : (i ^ 0x7fffffff);
}
__device__ __forceinline__ float fdec(int i) {
    return __int_as_float(i >= 0 ? i : (i ^ 0x7fffffff));
}
__device__ __forceinline__ void red_add_v4(float* addr, float4 v) {
    asm volatile("red.global.add.v4.f32 [%0], {%1, %2, %3, %4};"
                 :: "l"(addr), "f"(v.x), "f"(v.y), "f"(v.z), "f"(v.w)
                 : "memory");
}

// ---------------------------------------------------------------------------
// init kernels
// ---------------------------------------------------------------------------
__global__ void fill_f32(float* p, size_t n) {
    size_t i = (size_t)blockIdx.x * blockDim.x + threadIdx.x;
    if (i < n) p[i] = 0.0f;
}
__global__ void fill_i32(int* p, size_t n, int v) {
    size_t i = (size_t)blockIdx.x * blockDim.x + threadIdx.x;
    if (i < n) p[i] = v;
}

// ---------------------------------------------------------------------------
// register-tiled SGEMM: C[M,N] = A[M,K] @ B[K,N]
// BM=BN=64, BK=16, TM=TN=4, 256 threads.
// ---------------------------------------------------------------------------
template<int BM, int BN, int BK, int TM, int TN>
__global__ void sgemm_kernel(const float* __restrict__ A,
                             const float* __restrict__ B,
                             float* __restrict__ C,
                             int M, int N, int K) {
    __shared__ float As[BK * BM];  // transposed: As[k*BM + m]
    __shared__ float Bs[BK * BN];  // Bs[k*BN + n]
    const int tid = threadIdx.x;
    const int bm  = blockIdx.y;
    const int bn  = blockIdx.x;
    const int tx  = tid % (BN / TN);
    const int ty  = tid / (BN / TN);

    // 256 threads load BM x BK A-tile as float4: row = tid/(BK/4), colgrp = tid%(BK/4)
    const int aRow = tid / (BK / 4);
    const int aCol = (tid % (BK / 4)) * 4;
    const int bRow = tid / (BN / 4);
    const int bCol = (tid % (BN / 4)) * 4;

    float acc[TM][TN];
#pragma unroll
    for (int i = 0; i < TM; i++)
#pragma unroll
        for (int j = 0; j < TN; j++) acc[i][j] = 0.0f;

    for (int k0 = 0; k0 < K; k0 += BK) {
        {
            int grow = bm * BM + aRow;
            float4 v = make_float4(0.f, 0.f, 0.f, 0.f);
            if (grow < M) v = *(const float4*)(A + (size_t)grow * K + k0 + aCol);
            As[(aCol + 0) * BM + aRow] = v.x;
            As[(aCol + 1) * BM + aRow] = v.y;
            As[(aCol + 2) * BM + aRow] = v.z;
            As[(aCol + 3) * BM + aRow] = v.w;
        }
        {
            float4 v = *(const float4*)(B + (size_t)(k0 + bRow) * N + bn * BN + bCol);
            *(float4*)(Bs + bRow * BN + bCol) = v;
        }
        __syncthreads();

        float rm[TM], rn[TN];
#pragma unroll
        for (int k = 0; k < BK; k++) {
#pragma unroll
            for (int i = 0; i < TM; i++) rm[i] = As[k * BM + ty * TM + i];
#pragma unroll
            for (int j = 0; j < TN; j++) rn[j] = Bs[k * BN + tx * TN + j];
#pragma unroll
            for (int i = 0; i < TM; i++)
#pragma unroll
                for (int j = 0; j < TN; j++) acc[i][j] = fmaf(rm[i], rn[j], acc[i][j]);
        }
        __syncthreads();
    }
#pragma unroll
    for (int i = 0; i < TM; i++) {
        int row = bm * BM + ty * TM + i;
        if (row < M) {
            float4 v = make_float4(acc[i][0], acc[i][1], acc[i][2], acc[i][3]);
            *(float4*)(C + (size_t)row * N + bn * BN + tx * TN) = v;
        }
    }
}

// ---------------------------------------------------------------------------
// per-(node,head) attention scores: one warp per (node,head)
// ---------------------------------------------------------------------------
template<int H, int C>
__global__ void attscore_kernel(const float* __restrict__ h,
                                const float* __restrict__ att_s,
                                const float* __restrict__ att_d,
                                float* __restrict__ asrc,
                                float* __restrict__ adst,
                                int n) {
    int w = (int)(((size_t)blockIdx.x * blockDim.x + threadIdx.x) >> 5);
    int lane = threadIdx.x & 31;
    if (w >= n * H) return;
    int node = w / H, hh = w % H;
    const float* row = h + (size_t)node * (H * C) + hh * C;
    const float* as  = att_s + hh * C;
    const float* ad  = att_d + hh * C;
    float ss = 0.f, sd = 0.f;
#pragma unroll
    for (int c = lane; c < C; c += 32) {
        float v = row[c];
        ss += v * as[c];
        sd += v * ad[c];
    }
#pragma unroll
    for (int o = 16; o; o >>= 1) {
        ss += __shfl_down_sync(0xffffffffu, ss, o);
        sd += __shfl_down_sync(0xffffffffu, sd, o);
    }
    if (lane == 0) { asrc[w] = ss; adst[w] = sd; }
}

// ---------------------------------------------------------------------------
// edge pass 1: segment max of leaky_relu(asrc[src]+adst[dst]) over dst
// ---------------------------------------------------------------------------
template<int H>
__global__ void pass_max_kernel(const int* __restrict__ esrc,
                                const int* __restrict__ edst, int e, int et,
                                const float* __restrict__ asrc,
                                const float* __restrict__ adst,
                                int* __restrict__ amax) {
    int idx = blockIdx.x * blockDim.x + threadIdx.x;
    if (idx >= et) return;
    int s, d;
    if (idx < e) { s = esrc[idx]; d = edst[idx]; }
    else         { s = d = idx - e; }
#pragma unroll
    for (int h = 0; h < H; h++) {
        float a = asrc[s * H + h] + adst[d * H + h];
        a = a > 0.f ? a : 0.2f * a;
        atomicMax(&amax[d * H + h], fenc(a));
    }
}

// ---------------------------------------------------------------------------
// edge pass 2: ealpha = exp(alpha - amax[dst]); denom += ealpha; store ealpha
// ---------------------------------------------------------------------------
template<int H>
__global__ void pass_sum_kernel(const int* __restrict__ esrc,
                                const int* __restrict__ edst, int e, int et,
                                const float* __restrict__ asrc,
                                const float* __restrict__ adst,
                                const int* __restrict__ amax,
                                float* __restrict__ den,
                                float* __restrict__ ecoef) {
    int idx = blockIdx.x * blockDim.x + threadIdx.x;
    if (idx >= et) return;
    int s, d;
    if (idx < e) { s = esrc[idx]; d = edst[idx]; }
    else         { s = d = idx - e; }
#pragma unroll
    for (int h = 0; h < H; h++) {
        float a = asrc[s * H + h] + adst[d * H + h];
        a = a > 0.f ? a : 0.2f * a;
        float ea = __expf(a - fdec(amax[d * H + h]));
        atomicAdd(&den[d * H + h], ea);
        ecoef[(size_t)idx * H + h] = ea;
    }
}

// ---------------------------------------------------------------------------
// edge pass 3: agg[dst] += h[src] * (ealpha/denom[dst]); one warp per edge,
// vectorized float4 gather + red.global.add.v4.f32 scatter.
// ---------------------------------------------------------------------------
template<int H, int C>
__global__ void pass_agg_kernel(const int* __restrict__ esrc,
                                const int* __restrict__ edst, int e, int et,
                                const float* __restrict__ hsrc,
                                const float* __restrict__ den,
                                const float* __restrict__ ecoef,
                                float* __restrict__ agg) {
    int w = (int)(((size_t)blockIdx.x * blockDim.x + threadIdx.x) >> 5);
    int lane = threadIdx.x & 31;
    if (w >= et) return;
    int s, d;
    if (w < e) { s = esrc[w]; d = edst[w]; }
    else       { s = d = w - e; }
    float coef[H];
#pragma unroll
    for (int h = 0; h < H; h++)
        coef[h] = ecoef[(size_t)w * H + h] / (den[d * H + h] + 1e-16f);
    const float* hr = hsrc + (size_t)s * (H * C);
    float* ar = agg + (size_t)d * (H * C);
#pragma unroll
    for (int k = 0; k < (H * C) / 128; k++) {
        int c4 = (lane + k * 32) * 4;               // float4-aligned channel offset
        float cf = coef[c4 / C];                    // C % 4 == 0, same head in a float4
        float4 hv = *(const float4*)(hr + c4);
        red_add_v4(ar + c4, make_float4(hv.x * cf, hv.y * cf, hv.z * cf, hv.w * cf));
    }
}

// ---------------------------------------------------------------------------
// bias + ELU, in place
// ---------------------------------------------------------------------------
__global__ void bias_elu_kernel(float* __restrict__ a, const float* __restrict__ b,
                                size_t total, int cols) {
    size_t i = (size_t)blockIdx.x * blockDim.x + threadIdx.x;
    if (i >= total) return;
    float v = a[i] + b[i % cols];
    a[i] = v > 0.f ? v : expm1f(v);
}

// ---------------------------------------------------------------------------
// pooling
// ---------------------------------------------------------------------------
__global__ void count_kernel(const int* __restrict__ batch, int n,
                             float* __restrict__ cnt) {
    __shared__ int sc[NG];
    if (threadIdx.x < NG) sc[threadIdx.x] = 0;
    __syncthreads();
    int i = blockIdx.x * blockDim.x + threadIdx.x;
    if (i < n) atomicAdd(&sc[batch[i]], 1);
    __syncthreads();
    if (threadIdx.x < NG && sc[threadIdx.x])
        atomicAdd(&cnt[threadIdx.x], (float)sc[threadIdx.x]);
}

#define POOL_NODES_PER_BLOCK 512
__global__ void pool_sum_kernel(const float* __restrict__ h,
                                const int* __restrict__ batch, int n,
                                float* __restrict__ pool) {
    int c = threadIdx.x;  // 128 threads = channels
    int start = blockIdx.x * POOL_NODES_PER_BLOCK;
    int end = start + POOL_NODES_PER_BLOCK;
    if (end > n) end = n;
    float acc = 0.f;
    int cur = -1;
    for (int i = start; i < end; i++) {
        int g = batch[i];
        if (g != cur) {
            if (cur >= 0) atomicAdd(&pool[cur * C2_ + c], acc);
            acc = 0.f;
            cur = g;
        }
        acc += h[(size_t)i * C2_ + c];
    }
    if (cur >= 0) atomicAdd(&pool[cur * C2_ + c], acc);
}

// ---------------------------------------------------------------------------
// final linear head
// ---------------------------------------------------------------------------
__global__ void final_kernel(const float* __restrict__ pool,
                             const float* __restrict__ cnt,
                             const float* __restrict__ w,
                             const float* __restrict__ b,
                             float* __restrict__ out) {
    int t = threadIdx.x;
    if (t >= NG * NCLS) return;
    int g = t / NCLS, k = t % NCLS;
    float s = 0.f;
#pragma unroll 8
    for (int c = 0; c < C2_; c++) s += pool[g * C2_ + c] * w[c * NCLS + k];
    float n = cnt[g];
    out[t] = s / (n > 1.f ? n : 1.f) + b[k];
}

// ---------------------------------------------------------------------------
// launch
// ---------------------------------------------------------------------------
extern "C" void kernel_launch(void* const* d_in, const int* in_sizes, int n_in,
                              void* d_out, int out_size) {
    const float* x   = (const float*)d_in[0];
    const int*   ei  = (const int*)d_in[1];   // int32: JAX x64 disabled
    const int*   bat = (const int*)d_in[2];   // int32
    const float* W1  = (const float*)d_in[3];
    const float* as1 = (const float*)d_in[4];
    const float* ad1 = (const float*)d_in[5];
    const float* b1  = (const float*)d_in[6];
    const float* W2  = (const float*)d_in[7];
    const float* as2 = (const float*)d_in[8];
    const float* ad2 = (const float*)d_in[9];
    const float* b2  = (const float*)d_in[10];
    const float* lw  = (const float*)d_in[11];
    const float* lb  = (const float*)d_in[12];
    float* out = (float*)d_out;

    const int n  = in_sizes[0] / F_IN;   // 50000
    const int e  = in_sizes[1] / 2;      // 800000
    const int et = e + n;
    const int* esrc = ei;
    const int* edst = ei + e;

    float* base;
    cudaGetSymbolAddress((void**)&base, g_scratch);
    float* h1    = base + OFF_H1;
    float* h2    = base + OFF_H2;
    float* asrc1 = base + OFF_ASRC1;
    float* adst1 = base + OFF_ADST1;
    float* asrc2 = base + OFF_ASRC2;
    float* adst2 = base + OFF_ADST2;
    float* eco1  = base + OFF_ECO1;
    float* eco2  = base + OFF_ECO2;
    float* agg1  = base + OFF_AGG1;
    float* agg2  = base + OFF_AGG2;
    float* den1  = base + OFF_DEN1;
    float* den2  = base + OFF_DEN2;
    float* pool  = base + OFF_POOL;
    float* cnt   = base + OFF_CNT;
    int*   amax1 = (int*)(base + OFF_AMAX);
    int*   amax2 = amax1 + (size_t)NV * 4;

    // --- init ---
    {
        int bs = 256;
        fill_f32<<<(unsigned)((ZERO_COUNT + bs - 1) / bs), bs>>>(base + OFF_ZERO, ZERO_COUNT);
        fill_i32<<<(unsigned)((AMAX_COUNT + bs - 1) / bs), bs>>>(amax1, AMAX_COUNT, (int)0x80000000);
    }

    // --- layer 1 ---
    {
        dim3 grid(HC1 / 64, (n + 63) / 64);
        sgemm_kernel<64, 64, 16, 4, 4><<<grid, 256>>>(x, W1, h1, n, HC1, F_IN);
    }
    {
        int warps = n * H1_;
        attscore_kernel<H1_, C1_><<<(warps * 32 + 255) / 256, 256>>>(h1, as1, ad1, asrc1, adst1, n);
    }
    pass_max_kernel<H1_><<<(et + 255) / 256, 256>>>(esrc, edst, e, et, asrc1, adst1, amax1);
    pass_sum_kernel<H1_><<<(et + 255) / 256, 256>>>(esrc, edst, e, et, asrc1, adst1, amax1, den1, eco1);
    {
        size_t threads = (size_t)et * 32;
        pass_agg_kernel<H1_, C1_><<<(unsigned)((threads + 255) / 256), 256>>>(
            esrc, edst, e, et, h1, den1, eco1, agg1);
    }
    {
        size_t total = (size_t)n * HC1;
        bias_elu_kernel<<<(unsigned)((total + 255) / 256), 256>>>(agg1, b1, total, HC1);
    }

    // --- layer 2 ---
    {
        dim3 grid(C2_ / 64, (n + 63) / 64);
        sgemm_kernel<64, 64, 16, 4, 4><<<grid, 256>>>(agg1, W2, h2, n, C2_, HC1);
    }
    attscore_kernel<1, C2_><<<(n * 32 + 255) / 256, 256>>>(h2, as2, ad2, asrc2, adst2, n);
    pass_max_kernel<1><<<(et + 255) / 256, 256>>>(esrc, edst, e, et, asrc2, adst2, amax2);
    pass_sum_kernel<1><<<(et + 255) / 256, 256>>>(esrc, edst, e, et, asrc2, adst2, amax2, den2, eco2);
    {
        size_t threads = (size_t)et * 32;
        pass_agg_kernel<1, C2_><<<(unsigned)((threads + 255) / 256), 256>>>(
            esrc, edst, e, et, h2, den2, eco2, agg2);
    }
    {
        size_t total = (size_t)n * C2_;
        bias_elu_kernel<<<(unsigned)((total + 255) / 256), 256>>>(agg2, b2, total, C2_);
    }

    // --- pooling + head ---
    count_kernel<<<(n + 255) / 256, 256>>>(bat, n, cnt);
    pool_sum_kernel<<<(n + POOL_NODES_PER_BLOCK - 1) / POOL_NODES_PER_BLOCK, C2_>>>(agg2, bat, n, pool);
    final_kernel<<<1, NG * NCLS>>>(pool, cnt, lw, lb, out);
}

// round 3
// speedup vs baseline: 1.1729x; 1.1729x over previous
#include <cuda_runtime.h>
#include <cuda_bf16.h>
#include <math.h>

// ---------------------------------------------------------------------------
// Problem constants
// ---------------------------------------------------------------------------
#define NV    50000      // nodes
#define NE    800000     // edges (before self loops)
#define ET    (NE + NV)  // edges + self loops
#define F_IN  128
#define H1_   4
#define C1_   64
#define HC1   256        // H1*C1
#define C2_   128
#define NG    32         // graphs
#define NCLS  5

// ---------------------------------------------------------------------------
// Scratch (floats + ints in one __device__ buffer)
// ---------------------------------------------------------------------------
static const size_t OFF_H1    = 0;
static const size_t OFF_OUT1  = OFF_H1   + (size_t)NV * HC1;
static const size_t OFF_H2    = OFF_OUT1 + (size_t)NV * HC1;
static const size_t OFF_ASRC1 = OFF_H2   + (size_t)NV * C2_;
static const size_t OFF_ADST1 = OFF_ASRC1 + (size_t)NV * H1_;
static const size_t OFF_ASRC2 = OFF_ADST1 + (size_t)NV * H1_;
static const size_t OFF_ADST2 = OFF_ASRC2 + (size_t)NV;
static const size_t OFF_POOL  = OFF_ADST2 + (size_t)NV;          // zero region start
static const size_t OFF_CNT   = OFF_POOL + (size_t)NG * C2_;
static const size_t ZERO_CNT  = OFF_CNT + NG - OFF_POOL;
// int region
static const size_t OFF_DEG    = OFF_CNT + NG;
static const size_t OFF_ROWPTR = OFF_DEG + NV;
static const size_t OFF_WOFS   = OFF_ROWPTR + NV + 1;
static const size_t OFF_COL    = OFF_WOFS + NV;
static const size_t TOTAL_F    = OFF_COL + ET;

__device__ __align__(128) float g_scratch[TOTAL_F];

// ---------------------------------------------------------------------------
// helpers
// ---------------------------------------------------------------------------
__device__ __forceinline__ int fenc(float f) {
    int i = __float_as_int(f);
    return i >= 0 ? i : (i ^ 0x7fffffff);
}
__device__ __forceinline__ float fdec(int i) {
    return __int_as_float(i >= 0 ? i : (i ^ 0x7fffffff));
}

// ---------------------------------------------------------------------------
// fills
// ---------------------------------------------------------------------------
__global__ void fill_f32(float* p, size_t n) {
    size_t i = (size_t)blockIdx.x * blockDim.x + threadIdx.x;
    if (i < n) p[i] = 0.0f;
}
__global__ void fill_i32(int* p, size_t n, int v) {
    size_t i = (size_t)blockIdx.x * blockDim.x + threadIdx.x;
    if (i < n) p[i] = v;
}

// ---------------------------------------------------------------------------
// CSR build: degree histogram (deg pre-initialized to 1 for self loop),
// single-block scan, row-offset copy, scatter.
// ---------------------------------------------------------------------------
__global__ void deg_kernel(const int* __restrict__ edst, int e, int* deg) {
    int i = blockIdx.x * blockDim.x + threadIdx.x;
    if (i < e) atomicAdd(&deg[edst[i]], 1);
}

__global__ void scan_kernel(const int* __restrict__ deg, int* rowptr, int n) {
    __shared__ int buf[1024];
    __shared__ int carry;
    if (threadIdx.x == 0) { carry = 0; rowptr[0] = 0; }
    __syncthreads();
    for (int base = 0; base < n; base += 1024) {
        int i = base + threadIdx.x;
        int v = (i < n) ? deg[i] : 0;
        buf[threadIdx.x] = v;
        __syncthreads();
#pragma unroll
        for (int off = 1; off < 1024; off <<= 1) {
            int t = (threadIdx.x >= off) ? buf[threadIdx.x - off] : 0;
            __syncthreads();
            buf[threadIdx.x] += t;
            __syncthreads();
        }
        if (i < n) rowptr[i + 1] = buf[threadIdx.x] + carry;
        __syncthreads();
        if (threadIdx.x == 0) carry += buf[1023];
        __syncthreads();
    }
}

__global__ void copy_i32(const int* __restrict__ src, int* dst, int n) {
    int i = blockIdx.x * blockDim.x + threadIdx.x;
    if (i < n) dst[i] = src[i];
}

__global__ void scatter_kernel(const int* __restrict__ esrc,
                               const int* __restrict__ edst, int e, int et,
                               int* wofs, int* col) {
    int i = blockIdx.x * blockDim.x + threadIdx.x;
    if (i >= et) return;
    int s, d;
    if (i < e) { s = esrc[i]; d = edst[i]; }
    else       { s = d = i - e; }
    int pos = atomicAdd(&wofs[d], 1);
    col[pos] = s;
}

// ---------------------------------------------------------------------------
// SGEMM: C[M,N] = A[M,K] @ B[K,N]; 128x128x16 tile, 8x8/thread, 256 threads.
// N % 128 == 0, K % 16 == 0; M guarded.
// ---------------------------------------------------------------------------
__global__ __launch_bounds__(256, 2)
void sgemm128_kernel(const float* __restrict__ A, const float* __restrict__ B,
                     float* __restrict__ C, int M, int N, int K) {
    const int BM = 128, BN = 128, BK = 16;
    __shared__ float As[BK][BM];
    __shared__ float Bs[BK][BN];
    const int tid = threadIdx.x;
    const int bx = blockIdx.x, by = blockIdx.y;
    const int tx = tid % 16;
    const int ty = tid / 16;

    const int aRow = tid / 4;          // 0..63
    const int aCol = (tid % 4) * 4;    // 0,4,8,12
    const int bRow = tid / 32;         // 0..7
    const int bCol = (tid % 32) * 4;   // 0..124

    float acc[8][8];
#pragma unroll
    for (int i = 0; i < 8; i++)
#pragma unroll
        for (int j = 0; j < 8; j++) acc[i][j] = 0.f;

    for (int k0 = 0; k0 < K; k0 += BK) {
#pragma unroll
        for (int r = 0; r < BM; r += 64) {
            int grow = by * BM + aRow + r;
            float4 v = make_float4(0.f, 0.f, 0.f, 0.f);
            if (grow < M) v = *(const float4*)(A + (size_t)grow * K + k0 + aCol);
            As[aCol + 0][aRow + r] = v.x;
            As[aCol + 1][aRow + r] = v.y;
            As[aCol + 2][aRow + r] = v.z;
            As[aCol + 3][aRow + r] = v.w;
        }
#pragma unroll
        for (int r = 0; r < BK; r += 8) {
            float4 v = *(const float4*)(B + (size_t)(k0 + bRow + r) * N + bx * BN + bCol);
            *(float4*)&Bs[bRow + r][bCol] = v;
        }
        __syncthreads();

#pragma unroll
        for (int k = 0; k < BK; k++) {
            float rm[8], rn[8];
            *(float4*)&rm[0] = *(const float4*)&As[k][ty * 8 + 0];
            *(float4*)&rm[4] = *(const float4*)&As[k][ty * 8 + 4];
            *(float4*)&rn[0] = *(const float4*)&Bs[k][tx * 8 + 0];
            *(float4*)&rn[4] = *(const float4*)&Bs[k][tx * 8 + 4];
#pragma unroll
            for (int i = 0; i < 8; i++)
#pragma unroll
                for (int j = 0; j < 8; j++)
                    acc[i][j] = fmaf(rm[i], rn[j], acc[i][j]);
        }
        __syncthreads();
    }
#pragma unroll
    for (int i = 0; i < 8; i++) {
        int row = by * BM + ty * 8 + i;
        if (row < M) {
            float* cp = C + (size_t)row * N + bx * BN + tx * 8;
            *(float4*)(cp + 0) = make_float4(acc[i][0], acc[i][1], acc[i][2], acc[i][3]);
            *(float4*)(cp + 4) = make_float4(acc[i][4], acc[i][5], acc[i][6], acc[i][7]);
        }
    }
}

// ---------------------------------------------------------------------------
// attention scores: one warp per node, vectorized
// ---------------------------------------------------------------------------
template<int H, int C>
__global__ void attscore_kernel(const float* __restrict__ h,
                                const float* __restrict__ att_s,
                                const float* __restrict__ att_d,
                                float* __restrict__ asrc,
                                float* __restrict__ adst, int n) {
    constexpr int HC  = H * C;
    constexpr int PER = HC / 32;   // floats per lane (8 or 4)
    constexpr int SEG = C / PER;   // lanes per head (8 or 32)
    int node = (int)(((size_t)blockIdx.x * blockDim.x + threadIdx.x) >> 5);
    int lane = threadIdx.x & 31;
    if (node >= n) return;
    const float* row = h + (size_t)node * HC + lane * PER;
    const float* as  = att_s + lane * PER;
    const float* ad  = att_d + lane * PER;
    float ss = 0.f, sd = 0.f;
#pragma unroll
    for (int k = 0; k < PER; k += 4) {
        float4 hv = *(const float4*)(row + k);
        float4 av = *(const float4*)(as + k);
        float4 dv = *(const float4*)(ad + k);
        ss += hv.x * av.x + hv.y * av.y + hv.z * av.z + hv.w * av.w;
        sd += hv.x * dv.x + hv.y * dv.y + hv.z * dv.z + hv.w * dv.w;
    }
#pragma unroll
    for (int o = SEG / 2; o; o >>= 1) {
        ss += __shfl_down_sync(0xffffffffu, ss, o, SEG);
        sd += __shfl_down_sync(0xffffffffu, sd, o, SEG);
    }
    if ((lane % SEG) == 0) {
        int hh = lane / SEG;
        asrc[node * H + hh] = ss;
        adst[node * H + hh] = sd;
    }
}

// ---------------------------------------------------------------------------
// fused GAT layer: per-dst-node block. max -> exp/den -> weighted gather
// -> bias -> ELU -> store (or pool). HC threads per block.
// ---------------------------------------------------------------------------
template<int H, int C, bool POOL>
__global__ void gat_fused_kernel(const int* __restrict__ rowptr,
                                 const int* __restrict__ colidx,
                                 const float* __restrict__ h,
                                 const float* __restrict__ asrc,
                                 const float* __restrict__ adst,
                                 const float* __restrict__ bias,
                                 float* __restrict__ out,
                                 const int* __restrict__ batch,
                                 float* __restrict__ pool) {
    constexpr int HC = H * C;
    constexpr int CHUNK = 32;
    const int node = blockIdx.x;
    const int tid = threadIdx.x;
    __shared__ float s_adst[H];
    __shared__ int   s_max[H];
    __shared__ float s_den[H];
    __shared__ float sw[CHUNK * H];
    __shared__ int   sidx[CHUNK];

    const int row0 = rowptr[node];
    const int deg  = rowptr[node + 1] - row0;
    if (tid < H) {
        s_adst[tid] = adst[node * H + tid];
        s_max[tid]  = (int)0x80000000;
        s_den[tid]  = 0.f;
    }
    __syncthreads();

    // sweep A: per-head max of leaky_relu(asrc[src]+adst[node])
    for (int i = tid; i < deg * H; i += HC) {
        int s  = colidx[row0 + i / H];
        int hh = i % H;
        float a = asrc[s * H + hh] + s_adst[hh];
        a = a > 0.f ? a : 0.2f * a;
        atomicMax(&s_max[hh], fenc(a));
    }
    __syncthreads();

    const int myh = tid / C;
    float acc = 0.f;

    // sweep B: chunked weight compute + register aggregation
    for (int base = 0; base < deg; base += CHUNK) {
        int m = min(CHUNK, deg - base);
        if (tid < m * H) {
            int eidx = tid / H, hh = tid % H;
            int s = colidx[row0 + base + eidx];
            if (hh == 0) sidx[eidx] = s;
            float a = asrc[s * H + hh] + s_adst[hh];
            a = a > 0.f ? a : 0.2f * a;
            float w = __expf(a - fdec(s_max[hh]));
            sw[eidx * H + hh] = w;
            atomicAdd(&s_den[hh], w);
        }
        __syncthreads();
#pragma unroll 4
        for (int j = 0; j < m; j++)
            acc = fmaf(sw[j * H + myh], h[(size_t)sidx[j] * HC + tid], acc);
        __syncthreads();
    }

    float v = acc / (s_den[myh] + 1e-16f) + bias[tid];
    v = v > 0.f ? v : expm1f(v);
    if (POOL) {
        atomicAdd(&pool[batch[node] * HC + tid], v);
    } else {
        out[(size_t)node * HC + tid] = v;
    }
}

// ---------------------------------------------------------------------------
// graph-size counts + linear head
// ---------------------------------------------------------------------------
__global__ void count_kernel(const int* __restrict__ batch, int n,
                             float* __restrict__ cnt) {
    __shared__ int sc[NG];
    if (threadIdx.x < NG) sc[threadIdx.x] = 0;
    __syncthreads();
    int i = blockIdx.x * blockDim.x + threadIdx.x;
    if (i < n) atomicAdd(&sc[batch[i]], 1);
    __syncthreads();
    if (threadIdx.x < NG && sc[threadIdx.x])
        atomicAdd(&cnt[threadIdx.x], (float)sc[threadIdx.x]);
}

__global__ void final_kernel(const float* __restrict__ pool,
                             const float* __restrict__ cnt,
                             const float* __restrict__ w,
                             const float* __restrict__ b,
                             float* __restrict__ out) {
    int t = threadIdx.x;
    if (t >= NG * NCLS) return;
    int g = t / NCLS, k = t % NCLS;
    float s = 0.f;
#pragma unroll 8
    for (int c = 0; c < C2_; c++) s += pool[g * C2_ + c] * w[c * NCLS + k];
    float n = cnt[g];
    out[t] = s / (n > 1.f ? n : 1.f) + b[k];
}

// ---------------------------------------------------------------------------
// launch
// ---------------------------------------------------------------------------
extern "C" void kernel_launch(void* const* d_in, const int* in_sizes, int n_in,
                              void* d_out, int out_size) {
    const float* x   = (const float*)d_in[0];
    const int*   ei  = (const int*)d_in[1];   // int32 (JAX x64 disabled)
    const int*   bat = (const int*)d_in[2];
    const float* W1  = (const float*)d_in[3];
    const float* as1 = (const float*)d_in[4];
    const float* ad1 = (const float*)d_in[5];
    const float* b1  = (const float*)d_in[6];
    const float* W2  = (const float*)d_in[7];
    const float* as2 = (const float*)d_in[8];
    const float* ad2 = (const float*)d_in[9];
    const float* b2  = (const float*)d_in[10];
    const float* lw  = (const float*)d_in[11];
    const float* lb  = (const float*)d_in[12];
    float* out = (float*)d_out;

    const int n  = in_sizes[0] / F_IN;   // 50000
    const int e  = in_sizes[1] / 2;      // 800000
    const int et = e + n;
    const int* esrc = ei;
    const int* edst = ei + e;

    float* base;
    cudaGetSymbolAddress((void**)&base, g_scratch);
    float* h1    = base + OFF_H1;
    float* out1  = base + OFF_OUT1;
    float* h2    = base + OFF_H2;
    float* asrc1 = base + OFF_ASRC1;
    float* adst1 = base + OFF_ADST1;
    float* asrc2 = base + OFF_ASRC2;
    float* adst2 = base + OFF_ADST2;
    float* pool  = base + OFF_POOL;
    float* cnt   = base + OFF_CNT;
    int* deg     = (int*)(base + OFF_DEG);
    int* rowptr  = (int*)(base + OFF_ROWPTR);
    int* wofs    = (int*)(base + OFF_WOFS);
    int* col     = (int*)(base + OFF_COL);

    // --- init + CSR build ---
    fill_f32<<<(unsigned)((ZERO_CNT + 255) / 256), 256>>>(pool, ZERO_CNT);
    fill_i32<<<(n + 255) / 256, 256>>>(deg, n, 1);            // self loop
    deg_kernel<<<(e + 255) / 256, 256>>>(edst, e, deg);
    scan_kernel<<<1, 1024>>>(deg, rowptr, n);
    copy_i32<<<(n + 255) / 256, 256>>>(rowptr, wofs, n);
    scatter_kernel<<<(et + 255) / 256, 256>>>(esrc, edst, e, et, wofs, col);

    // --- layer 1 ---
    {
        dim3 grid(HC1 / 128, (n + 127) / 128);
        sgemm128_kernel<<<grid, 256>>>(x, W1, h1, n, HC1, F_IN);
    }
    attscore_kernel<H1_, C1_><<<(n * 32 + 255) / 256, 256>>>(h1, as1, ad1, asrc1, adst1, n);
    gat_fused_kernel<H1_, C1_, false><<<n, HC1>>>(rowptr, col, h1, asrc1, adst1,
                                                  b1, out1, nullptr, nullptr);

    // --- layer 2 ---
    {
        dim3 grid(C2_ / 128, (n + 127) / 128);
        sgemm128_kernel<<<grid, 256>>>(out1, W2, h2, n, C2_, HC1);
    }
    attscore_kernel<1, C2_><<<(n * 32 + 255) / 256, 256>>>(h2, as2, ad2, asrc2, adst2, n);
    gat_fused_kernel<1, C2_, true><<<n, C2_>>>(rowptr, col, h2, asrc2, adst2,
                                               b2, nullptr, bat, pool);

    // --- head ---
    count_kernel<<<(n + 255) / 256, 256>>>(bat, n, cnt);
    final_kernel<<<1, NG * NCLS>>>(pool, cnt, lw, lb, out);
}

// round 4
// speedup vs baseline: 1.1766x; 1.0031x over previous
#include <cuda_runtime.h>
#include <cuda_bf16.h>
#include <math.h>

// ---------------------------------------------------------------------------
// Problem constants
// ---------------------------------------------------------------------------
#define NV    50000      // nodes
#define NE    800000     // edges (before self loops)
#define ET    (NE + NV)  // edges + self loops
#define F_IN  128
#define H1_   4
#define C1_   64
#define HC1   256        // H1*C1
#define C2_   128
#define NG    32         // graphs
#define NCLS  5

// ---------------------------------------------------------------------------
// Scratch (floats + ints in one __device__ buffer)
// ---------------------------------------------------------------------------
static const size_t OFF_H1    = 0;
static const size_t OFF_OUT1  = OFF_H1   + (size_t)NV * HC1;
static const size_t OFF_H2    = OFF_OUT1 + (size_t)NV * HC1;
static const size_t OFF_ASRC1 = OFF_H2   + (size_t)NV * C2_;
static const size_t OFF_ADST1 = OFF_ASRC1 + (size_t)NV * H1_;
static const size_t OFF_ASRC2 = OFF_ADST1 + (size_t)NV * H1_;
static const size_t OFF_ADST2 = OFF_ASRC2 + (size_t)NV;
static const size_t OFF_POOL  = OFF_ADST2 + (size_t)NV;          // zero region start
static const size_t OFF_CNT   = OFF_POOL + (size_t)NG * C2_;
static const size_t ZERO_CNT  = OFF_CNT + NG - OFF_POOL;
// int region
static const size_t OFF_DEG    = OFF_CNT + NG;
static const size_t OFF_ROWPTR = OFF_DEG + NV;
static const size_t OFF_WOFS   = OFF_ROWPTR + NV + 1;
static const size_t OFF_COL    = OFF_WOFS + NV;
static const size_t TOTAL_F    = OFF_COL + ET;

__device__ __align__(128) float g_scratch[TOTAL_F];

// ---------------------------------------------------------------------------
// helpers
// ---------------------------------------------------------------------------
__device__ __forceinline__ int fenc(float f) {
    int i = __float_as_int(f);
    return i >= 0 ? i : (i ^ 0x7fffffff);
}
__device__ __forceinline__ float fdec(int i) {
    return __int_as_float(i >= 0 ? i : (i ^ 0x7fffffff));
}

// ---------------------------------------------------------------------------
// fills
// ---------------------------------------------------------------------------
__global__ void fill_f32(float* p, size_t n) {
    size_t i = (size_t)blockIdx.x * blockDim.x + threadIdx.x;
    if (i < n) p[i] = 0.0f;
}
__global__ void fill_i32(int* p, size_t n, int v) {
    size_t i = (size_t)blockIdx.x * blockDim.x + threadIdx.x;
    if (i < n) p[i] = v;
}

// ---------------------------------------------------------------------------
// CSR build: degree histogram (deg pre-initialized to 1 for self loop),
// single-block scan, row-offset copy, scatter.
// ---------------------------------------------------------------------------
__global__ void deg_kernel(const int* __restrict__ edst, int e, int* deg) {
    int i = blockIdx.x * blockDim.x + threadIdx.x;
    if (i < e) atomicAdd(&deg[edst[i]], 1);
}

__global__ void scan_kernel(const int* __restrict__ deg, int* rowptr, int n) {
    __shared__ int buf[1024];
    __shared__ int carry;
    if (threadIdx.x == 0) { carry = 0; rowptr[0] = 0; }
    __syncthreads();
    for (int base = 0; base < n; base += 1024) {
        int i = base + threadIdx.x;
        int v = (i < n) ? deg[i] : 0;
        buf[threadIdx.x] = v;
        __syncthreads();
#pragma unroll
        for (int off = 1; off < 1024; off <<= 1) {
            int t = (threadIdx.x >= off) ? buf[threadIdx.x - off] : 0;
            __syncthreads();
            buf[threadIdx.x] += t;
            __syncthreads();
        }
        if (i < n) rowptr[i + 1] = buf[threadIdx.x] + carry;
        __syncthreads();
        if (threadIdx.x == 0) carry += buf[1023];
        __syncthreads();
    }
}

__global__ void copy_i32(const int* __restrict__ src, int* dst, int n) {
    int i = blockIdx.x * blockDim.x + threadIdx.x;
    if (i < n) dst[i] = src[i];
}

__global__ void scatter_kernel(const int* __restrict__ esrc,
                               const int* __restrict__ edst, int e, int et,
                               int* wofs, int* col) {
    int i = blockIdx.x * blockDim.x + threadIdx.x;
    if (i >= et) return;
    int s, d;
    if (i < e) { s = esrc[i]; d = edst[i]; }
    else       { s = d = i - e; }
    int pos = atomicAdd(&wofs[d], 1);
    col[pos] = s;
}

// ---------------------------------------------------------------------------
// SGEMM: C[M,N] = A[M,K] @ B[K,N]; 128x128x16 tile, 8x8/thread, 256 threads.
// N % 128 == 0, K % 16 == 0; M guarded.
// ---------------------------------------------------------------------------
__global__ __launch_bounds__(256, 2)
void sgemm128_kernel(const float* __restrict__ A, const float* __restrict__ B,
                     float* __restrict__ C, int M, int N, int K) {
    const int BM = 128, BN = 128, BK = 16;
    __shared__ float As[BK][BM];
    __shared__ float Bs[BK][BN];
    const int tid = threadIdx.x;
    const int bx = blockIdx.x, by = blockIdx.y;
    const int tx = tid % 16;
    const int ty = tid / 16;

    const int aRow = tid / 4;          // 0..63
    const int aCol = (tid % 4) * 4;    // 0,4,8,12
    const int bRow = tid / 32;         // 0..7
    const int bCol = (tid % 32) * 4;   // 0..124

    float acc[8][8];
#pragma unroll
    for (int i = 0; i < 8; i++)
#pragma unroll
        for (int j = 0; j < 8; j++) acc[i][j] = 0.f;

    for (int k0 = 0; k0 < K; k0 += BK) {
#pragma unroll
        for (int r = 0; r < BM; r += 64) {
            int grow = by * BM + aRow + r;
            float4 v = make_float4(0.f, 0.f, 0.f, 0.f);
            if (grow < M) v = *(const float4*)(A + (size_t)grow * K + k0 + aCol);
            As[aCol + 0][aRow + r] = v.x;
            As[aCol + 1][aRow + r] = v.y;
            As[aCol + 2][aRow + r] = v.z;
            As[aCol + 3][aRow + r] = v.w;
        }
#pragma unroll
        for (int r = 0; r < BK; r += 8) {
            float4 v = *(const float4*)(B + (size_t)(k0 + bRow + r) * N + bx * BN + bCol);
            *(float4*)&Bs[bRow + r][bCol] = v;
        }
        __syncthreads();

#pragma unroll
        for (int k = 0; k < BK; k++) {
            float rm[8], rn[8];
            *(float4*)&rm[0] = *(const float4*)&As[k][ty * 8 + 0];
            *(float4*)&rm[4] = *(const float4*)&As[k][ty * 8 + 4];
            *(float4*)&rn[0] = *(const float4*)&Bs[k][tx * 8 + 0];
            *(float4*)&rn[4] = *(const float4*)&Bs[k][tx * 8 + 4];
#pragma unroll
            for (int i = 0; i < 8; i++)
#pragma unroll
                for (int j = 0; j < 8; j++)
                    acc[i][j] = fmaf(rm[i], rn[j], acc[i][j]);
        }
        __syncthreads();
    }
#pragma unroll
    for (int i = 0; i < 8; i++) {
        int row = by * BM + ty * 8 + i;
        if (row < M) {
            float* cp = C + (size_t)row * N + bx * BN + tx * 8;
            *(float4*)(cp + 0) = make_float4(acc[i][0], acc[i][1], acc[i][2], acc[i][3]);
            *(float4*)(cp + 4) = make_float4(acc[i][4], acc[i][5], acc[i][6], acc[i][7]);
        }
    }
}

// ---------------------------------------------------------------------------
// attention scores: one warp per node, vectorized
// ---------------------------------------------------------------------------
template<int H, int C>
__global__ void attscore_kernel(const float* __restrict__ h,
                                const float* __restrict__ att_s,
                                const float* __restrict__ att_d,
                                float* __restrict__ asrc,
                                float* __restrict__ adst, int n) {
    constexpr int HC  = H * C;
    constexpr int PER = HC / 32;   // floats per lane (8 or 4)
    constexpr int SEG = C / PER;   // lanes per head (8 or 32)
    int node = (int)(((size_t)blockIdx.x * blockDim.x + threadIdx.x) >> 5);
    int lane = threadIdx.x & 31;
    if (node >= n) return;
    const float* row = h + (size_t)node * HC + lane * PER;
    const float* as  = att_s + lane * PER;
    const float* ad  = att_d + lane * PER;
    float ss = 0.f, sd = 0.f;
#pragma unroll
    for (int k = 0; k < PER; k += 4) {
        float4 hv = *(const float4*)(row + k);
        float4 av = *(const float4*)(as + k);
        float4 dv = *(const float4*)(ad + k);
        ss += hv.x * av.x + hv.y * av.y + hv.z * av.z + hv.w * av.w;
        sd += hv.x * dv.x + hv.y * dv.y + hv.z * dv.z + hv.w * dv.w;
    }
#pragma unroll
    for (int o = SEG / 2; o; o >>= 1) {
        ss += __shfl_down_sync(0xffffffffu, ss, o, SEG);
        sd += __shfl_down_sync(0xffffffffu, sd, o, SEG);
    }
    if ((lane % SEG) == 0) {
        int hh = lane / SEG;
        asrc[node * H + hh] = ss;
        adst[node * H + hh] = sd;
    }
}

// ---------------------------------------------------------------------------
// fused GAT layer: per-dst-node block. max -> exp/den -> weighted gather
// -> bias -> ELU -> store (or pool). HC threads per block.
// ---------------------------------------------------------------------------
template<int H, int C, bool POOL>
__global__ void gat_fused_kernel(const int* __restrict__ rowptr,
                                 const int* __restrict__ colidx,
                                 const float* __restrict__ h,
                                 const float* __restrict__ asrc,
                                 const float* __restrict__ adst,
                                 const float* __restrict__ bias,
                                 float* __restrict__ out,
                                 const int* __restrict__ batch,
                                 float* __restrict__ pool) {
    constexpr int HC = H * C;
    constexpr int CHUNK = 32;
    const int node = blockIdx.x;
    const int tid = threadIdx.x;
    __shared__ float s_adst[H];
    __shared__ int   s_max[H];
    __shared__ float s_den[H];
    __shared__ float sw[CHUNK * H];
    __shared__ int   sidx[CHUNK];

    const int row0 = rowptr[node];
    const int deg  = rowptr[node + 1] - row0;
    if (tid < H) {
        s_adst[tid] = adst[node * H + tid];
        s_max[tid]  = (int)0x80000000;
        s_den[tid]  = 0.f;
    }
    __syncthreads();

    // sweep A: per-head max of leaky_relu(asrc[src]+adst[node])
    for (int i = tid; i < deg * H; i += HC) {
        int s  = colidx[row0 + i / H];
        int hh = i % H;
        float a = asrc[s * H + hh] + s_adst[hh];
        a = a > 0.f ? a : 0.2f * a;
        atomicMax(&s_max[hh], fenc(a));
    }
    __syncthreads();

    const int myh = tid / C;
    float acc = 0.f;

    // sweep B: chunked weight compute + register aggregation
    for (int base = 0; base < deg; base += CHUNK) {
        int m = min(CHUNK, deg - base);
        if (tid < m * H) {
            int eidx = tid / H, hh = tid % H;
            int s = colidx[row0 + base + eidx];
            if (hh == 0) sidx[eidx] = s;
            float a = asrc[s * H + hh] + s_adst[hh];
            a = a > 0.f ? a : 0.2f * a;
            float w = __expf(a - fdec(s_max[hh]));
            sw[eidx * H + hh] = w;
            atomicAdd(&s_den[hh], w);
        }
        __syncthreads();
#pragma unroll 4
        for (int j = 0; j < m; j++)
            acc = fmaf(sw[j * H + myh], h[(size_t)sidx[j] * HC + tid], acc);
        __syncthreads();
    }

    float v = acc / (s_den[myh] + 1e-16f) + bias[tid];
    v = v > 0.f ? v : expm1f(v);
    if (POOL) {
        atomicAdd(&pool[batch[node] * HC + tid], v);
    } else {
        out[(size_t)node * HC + tid] = v;
    }
}

// ---------------------------------------------------------------------------
// graph-size counts + linear head
// ---------------------------------------------------------------------------
__global__ void count_kernel(const int* __restrict__ batch, int n,
                             float* __restrict__ cnt) {
    __shared__ int sc[NG];
    if (threadIdx.x < NG) sc[threadIdx.x] = 0;
    __syncthreads();
    int i = blockIdx.x * blockDim.x + threadIdx.x;
    if (i < n) atomicAdd(&sc[batch[i]], 1);
    __syncthreads();
    if (threadIdx.x < NG && sc[threadIdx.x])
        atomicAdd(&cnt[threadIdx.x], (float)sc[threadIdx.x]);
}

__global__ void final_kernel(const float* __restrict__ pool,
                             const float* __restrict__ cnt,
                             const float* __restrict__ w,
                             const float* __restrict__ b,
                             float* __restrict__ out) {
    int t = threadIdx.x;
    if (t >= NG * NCLS) return;
    int g = t / NCLS, k = t % NCLS;
    float s = 0.f;
#pragma unroll 8
    for (int c = 0; c < C2_; c++) s += pool[g * C2_ + c] * w[c * NCLS + k];
    float n = cnt[g];
    out[t] = s / (n > 1.f ? n : 1.f) + b[k];
}

// ---------------------------------------------------------------------------
// launch
// ---------------------------------------------------------------------------
extern "C" void kernel_launch(void* const* d_in, const int* in_sizes, int n_in,
                              void* d_out, int out_size) {
    const float* x   = (const float*)d_in[0];
    const int*   ei  = (const int*)d_in[1];   // int32 (JAX x64 disabled)
    const int*   bat = (const int*)d_in[2];
    const float* W1  = (const float*)d_in[3];
    const float* as1 = (const float*)d_in[4];
    const float* ad1 = (const float*)d_in[5];
    const float* b1  = (const float*)d_in[6];
    const float* W2  = (const float*)d_in[7];
    const float* as2 = (const float*)d_in[8];
    const float* ad2 = (const float*)d_in[9];
    const float* b2  = (const float*)d_in[10];
    const float* lw  = (const float*)d_in[11];
    const float* lb  = (const float*)d_in[12];
    float* out = (float*)d_out;

    const int n  = in_sizes[0] / F_IN;   // 50000
    const int e  = in_sizes[1] / 2;      // 800000
    const int et = e + n;
    const int* esrc = ei;
    const int* edst = ei + e;

    float* base;
    cudaGetSymbolAddress((void**)&base, g_scratch);
    float* h1    = base + OFF_H1;
    float* out1  = base + OFF_OUT1;
    float* h2    = base + OFF_H2;
    float* asrc1 = base + OFF_ASRC1;
    float* adst1 = base + OFF_ADST1;
    float* asrc2 = base + OFF_ASRC2;
    float* adst2 = base + OFF_ADST2;
    float* pool  = base + OFF_POOL;
    float* cnt   = base + OFF_CNT;
    int* deg     = (int*)(base + OFF_DEG);
    int* rowptr  = (int*)(base + OFF_ROWPTR);
    int* wofs    = (int*)(base + OFF_WOFS);
    int* col     = (int*)(base + OFF_COL);

    // --- init + CSR build ---
    fill_f32<<<(unsigned)((ZERO_CNT + 255) / 256), 256>>>(pool, ZERO_CNT);
    fill_i32<<<(n + 255) / 256, 256>>>(deg, n, 1);            // self loop
    deg_kernel<<<(e + 255) / 256, 256>>>(edst, e, deg);
    scan_kernel<<<1, 1024>>>(deg, rowptr, n);
    copy_i32<<<(n + 255) / 256, 256>>>(rowptr, wofs, n);
    scatter_kernel<<<(et + 255) / 256, 256>>>(esrc, edst, e, et, wofs, col);

    // --- layer 1 ---
    {
        dim3 grid(HC1 / 128, (n + 127) / 128);
        sgemm128_kernel<<<grid, 256>>>(x, W1, h1, n, HC1, F_IN);
    }
    attscore_kernel<H1_, C1_><<<(n * 32 + 255) / 256, 256>>>(h1, as1, ad1, asrc1, adst1, n);
    gat_fused_kernel<H1_, C1_, false><<<n, HC1>>>(rowptr, col, h1, asrc1, adst1,
                                                  b1, out1, nullptr, nullptr);

    // --- layer 2 ---
    {
        dim3 grid(C2_ / 128, (n + 127) / 128);
        sgemm128_kernel<<<grid, 256>>>(out1, W2, h2, n, C2_, HC1);
    }
    attscore_kernel<1, C2_><<<(n * 32 + 255) / 256, 256>>>(h2, as2, ad2, asrc2, adst2, n);
    gat_fused_kernel<1, C2_, true><<<n, C2_>>>(rowptr, col, h2, asrc2, adst2,
                                               b2, nullptr, bat, pool);

    // --- head ---
    count_kernel<<<(n + 255) / 256, 256>>>(bat, n, cnt);
    final_kernel<<<1, NG * NCLS>>>(pool, cnt, lw, lb, out);
}